// round 10
// baseline (speedup 1.0000x reference)
#include <cuda_runtime.h>

// StripePolynomial2d — GB300 sm_103a, round 8
//
// vs R7: batch dimension split across grid.y (4 batches/thread) to cut the
// dominant register groups in half (acc/mask/xl/xv) and reach 3 CTAs/SM
// (<=84 regs). Core f32x2 blend math and table-driven prologue unchanged.

#define NW 129
#define PLANE (512*512)

typedef unsigned long long u64;

__device__ __forceinline__ u64 pk(float a, float b) {
    u64 r;
    asm("mov.b64 %0, {%1, %2};" : "=l"(r) : "f"(a), "f"(b));
    return r;
}
__device__ __forceinline__ u64 ffma2(u64 a, u64 b, u64 c) {
    u64 d;
    asm("fma.rn.f32x2 %0, %1, %2, %3;" : "=l"(d) : "l"(a), "l"(b), "l"(c));
    return d;
}
__device__ __forceinline__ u64 fadd2(u64 a, u64 b) {
    u64 d;
    asm("add.rn.f32x2 %0, %1, %2;" : "=l"(d) : "l"(a), "l"(b));
    return d;
}
__device__ __forceinline__ void upk(u64 v, float& lo, float& hi) {
    asm("mov.b64 {%0, %1}, %2;" : "=f"(lo), "=f"(hi) : "l"(v));
}

// coefA[g][c][seg][o] : (a0,a1,a2,_) prescaled by 0.25
// coefD[g][c][seg][o] : coefA(seg+1) - coefA(seg)  (zero at seg=63)
__device__ float4 g_coefA[1728];
__device__ float4 g_coefD[1728];
// prologue tables: (X, d0, int_bits(seg*3), 0)
__device__ float4 g_pre0[512];    // index w        (stripe group 0)
__device__ float4 g_pre1[1023];   // index w+h (g1) and w-h+511 (g2)

__global__ void build_kernel(const float* __restrict__ Wt)
{
    int e = blockIdx.x * 256 + threadIdx.x;

    if (e < 1728) {
        int o = e % 3;
        int s = (e / 3) & 63;
        int c = (e / 192) % 3;
        int g = e / 576;

        auto coef_at = [&](int seg, float& a0, float& a1, float& a2) {
            int k = 2 * seg;
            float w0, w1, w2;
            if (g == 0) {
                const float* p0 = Wt + ((0 * 3 + o) * 3 + c) * NW + k;
                const float* p1 = Wt + ((1 * 3 + o) * 3 + c) * NW + k;
                w0 = p0[0] + p1[0];
                w1 = p0[1] + p1[1];
                w2 = p0[2] + p1[2];
            } else {
                const float* p = Wt + (((g + 1) * 3 + o) * 3 + c) * NW + k;
                w0 = p[0]; w1 = p[1]; w2 = p[2];
            }
            a0 = 0.25f * w1;
            a1 = 0.25f * (0.5f * (w2 - w0));
            a2 = 0.25f * (0.5f * (w0 + w2) - w1);
        };

        float a0, a1, a2;
        coef_at(s, a0, a1, a2);
        g_coefA[e] = make_float4(a0, a1, a2, 0.0f);

        float d0 = 0.0f, d1 = 0.0f, d2 = 0.0f;
        if (s < 63) {
            float b0, b1, b2;
            coef_at(s + 1, b0, b1, b2);
            d0 = b0 - a0; d1 = b1 - a1; d2 = b2 - a2;
        }
        g_coefD[e] = make_float4(d0, d1, d2, 0.0f);
        return;
    }

    // prologue tables (fp64 done once here, mirrors reference float64 grid math)
    const double RATIO = 512.0 / 513.0;
    float bb;
    float4* dst;
    if (e < 1728 + 512) {
        int i = e - 1728;
        bb = (float)(((double)i * RATIO / 511.0 - 0.5) * 512.0) * 0.125f + 32.0f;
        dst = &g_pre0[i];
    } else if (e < 1728 + 512 + 1023) {
        int i = e - (1728 + 512);
        bb = (float)(((double)i * RATIO / 1022.0 - 0.5) * 512.0) * 0.125f + 32.0f;
        dst = &g_pre1[i];
    } else {
        return;
    }
    float s0f = fminf(fmaxf(floorf(bb), 0.0f), 63.0f);
    float fb  = bb - s0f;                                 // exact
    float X   = (s0f < 63.0f) ? 8.0f * (1.0f - fb) : 1e30f;
    float d0  = 2.0f * fb - 1.0f;
    int   s3  = (int)s0f * 3;
    *dst = make_float4(X, d0, __int_as_float(s3), 0.0f);
}

__global__ __launch_bounds__(256, 3)
void stripe_poly_kernel(const float* __restrict__ x,
                        float* __restrict__ out)
{
    __shared__ float4 cA[1728];
    __shared__ float4 cD[1728];
    #pragma unroll
    for (int e = threadIdx.x; e < 1728; e += 256) {
        cA[e] = g_coefA[e];
        cD[e] = g_coefD[e];
    }
    __syncthreads();

    int pid = blockIdx.x * 256 + threadIdx.x;
    int w = pid >> 9;
    int h = pid & 511;
    int b0 = blockIdx.y * 4;

    // table-driven prologue
    float4 P0 = g_pre0[w];
    float4 P1 = g_pre1[w + h];
    float4 P2 = g_pre1[w - h + 511];

    float X[3];
    u64 dd2g[3];
    int offg[3];
    X[0] = P0.x; dd2g[0] = pk(P0.y, P0.y); offg[0] =        __float_as_int(P0.z);
    X[1] = P1.x; dd2g[1] = pk(P1.y, P1.y); offg[1] = 576  + __float_as_int(P1.z);
    X[2] = P2.x; dd2g[2] = pk(P2.y, P2.y); offg[2] = 1152 + __float_as_int(P2.z);

    const u64 Q2 = pk(0.25f, 0.25f);
    const u64 N2 = pk(-2.0f, -2.0f);

    u64 acc2[2][3];
    #pragma unroll
    for (int p = 0; p < 2; p++)
        #pragma unroll
        for (int o = 0; o < 3; o++)
            acc2[p][o] = 0ULL;

    #pragma unroll
    for (int c = 0; c < 3; c++) {
        float xv[4];
        #pragma unroll
        for (int b = 0; b < 4; b++)
            xv[b] = __ldg(x + ((b0 + b) * 3 + c) * PLANE + pid);
        u64 xv2[2];
        #pragma unroll
        for (int p = 0; p < 2; p++)
            xv2[p] = pk(xv[2 * p], xv[2 * p + 1]);

        #pragma unroll
        for (int g = 0; g < 3; g++) {
            int off = offg[g] + c * 192;
            float Xg = X[g];
            u64 dd2 = dd2g[g];

            u64 mf2[2], xl2[2];
            #pragma unroll
            for (int p = 0; p < 2; p++) {
                float m0 = (xv[2 * p]     >= Xg) ? 1.0f : 0.0f;
                float m1 = (xv[2 * p + 1] >= Xg) ? 1.0f : 0.0f;
                mf2[p] = pk(m0, m1);
                u64 t  = ffma2(Q2, xv2[p], dd2);
                xl2[p] = ffma2(N2, mf2[p], t);
            }

            #pragma unroll
            for (int o = 0; o < 3; o++) {
                float4 A = cA[off + o];
                float4 D = cD[off + o];
                u64 A0 = pk(A.x, A.x), A1 = pk(A.y, A.y), A2 = pk(A.z, A.z);
                u64 D0 = pk(D.x, D.x), D1 = pk(D.y, D.y), D2 = pk(D.z, D.z);
                #pragma unroll
                for (int p = 0; p < 2; p++) {
                    u64 q0 = ffma2(mf2[p], D0, A0);
                    u64 q1 = ffma2(mf2[p], D1, A1);
                    u64 q2 = ffma2(mf2[p], D2, A2);
                    u64 t  = ffma2(q2, xl2[p], q1);
                    t      = ffma2(t, xl2[p], q0);
                    acc2[p][o] = fadd2(acc2[p][o], t);
                }
            }
        }
    }

    #pragma unroll
    for (int p = 0; p < 2; p++)
        #pragma unroll
        for (int o = 0; o < 3; o++) {
            float lo, hi;
            upk(acc2[p][o], lo, hi);
            out[((b0 + 2 * p)     * 3 + o) * PLANE + pid] = lo;
            out[((b0 + 2 * p + 1) * 3 + o) * PLANE + pid] = hi;
        }
}

extern "C" void kernel_launch(void* const* d_in, const int* in_sizes, int n_in,
                              void* d_out, int out_size)
{
    const float* x  = (const float*)d_in[0];
    const float* Wt = (const float*)d_in[1];
    if (n_in >= 2 && in_sizes[0] == 4644) {
        Wt = (const float*)d_in[0];
        x  = (const float*)d_in[1];
    }
    float* out = (float*)d_out;

    build_kernel<<<13, 256>>>(Wt);     // 1728 coef + 512 + 1023 table entries
    dim3 grid((512 * 512) / 256, 2);
    stripe_poly_kernel<<<grid, 256>>>(x, out);
}

// round 12
// speedup vs baseline: 1.2376x; 1.2376x over previous
#include <cuda_runtime.h>

// StripePolynomial2d — GB300 sm_103a, round 9b (fix: no max.f32x2 in PTX)
//
// val = A_s(u) + relu(u-1) * (g1 + g2*u), u = 0.25x + d0 unclamped.
// relu via r' = t + |t| (= 2*relu(t)); factor 2 folded into G table.
// Lane-duplicated u64 coefficient table in global (L1-resident), LDG.128,
// no shared memory, no masks/selects. 8 batches/thread, grid 1024.

#define NW 129
#define PLANE (512*512)

typedef unsigned long long u64;

__device__ __forceinline__ u64 pk(float a, float b) {
    u64 r;
    asm("mov.b64 %0, {%1, %2};" : "=l"(r) : "f"(a), "f"(b));
    return r;
}
__device__ __forceinline__ u64 ffma2(u64 a, u64 b, u64 c) {
    u64 d;
    asm("fma.rn.f32x2 %0, %1, %2, %3;" : "=l"(d) : "l"(a), "l"(b), "l"(c));
    return d;
}
__device__ __forceinline__ u64 fadd2(u64 a, u64 b) {
    u64 d;
    asm("add.rn.f32x2 %0, %1, %2;" : "=l"(d) : "l"(a), "l"(b));
    return d;
}
__device__ __forceinline__ void upk(u64 v, float& lo, float& hi) {
    asm("mov.b64 {%0, %1}, %2;" : "=f"(lo), "=f"(hi) : "l"(v));
}
__device__ __forceinline__ u64 dup_bits(float v) {
    unsigned int b = __float_as_uint(v);
    return ((u64)b << 32) | (u64)b;
}

// table: per (g,c,seg,o): 6 u64 slots {A0A0, A1A1, A2A2, G1G1, G2G2, pad}
// (G pre-multiplied by 0.5 to absorb r' = 2*relu)
__device__ u64 g_tab[1728 * 6];
// prologue tables: (pad, d0, int_bits(seg*3), pad)
__device__ float4 g_pre0[512];    // index w        (stripe group 0)
__device__ float4 g_pre1[1023];   // index w+h (g1) and w-h+511 (g2)

__global__ void build_kernel(const float* __restrict__ Wt)
{
    int e = blockIdx.x * 256 + threadIdx.x;

    if (e < 1728) {
        int o = e % 3;
        int s = (e / 3) & 63;
        int c = (e / 192) % 3;
        int g = e / 576;

        auto coef_at = [&](int seg, float& a0, float& a1, float& a2) {
            int k = 2 * seg;
            float w0, w1, w2;
            if (g == 0) {
                const float* p0 = Wt + ((0 * 3 + o) * 3 + c) * NW + k;
                const float* p1 = Wt + ((1 * 3 + o) * 3 + c) * NW + k;
                w0 = p0[0] + p1[0];
                w1 = p0[1] + p1[1];
                w2 = p0[2] + p1[2];
            } else {
                const float* p = Wt + (((g + 1) * 3 + o) * 3 + c) * NW + k;
                w0 = p[0]; w1 = p[1]; w2 = p[2];
            }
            a0 = 0.25f * w1;
            a1 = 0.25f * (0.5f * (w2 - w0));
            a2 = 0.25f * (0.5f * (w0 + w2) - w1);
        };

        float a0, a1, a2;
        coef_at(s, a0, a1, a2);

        float g1 = 0.0f, g2 = 0.0f;
        if (s < 63) {
            float b0, b1, b2;
            coef_at(s + 1, b0, b1, b2);
            // B(u) = P_{s+1}(u-2) - P_s(u), B(1)=0 (continuity)
            float c1p = (b1 - 4.0f * b2) - a1;
            float c2p = b2 - a2;
            g2 = 0.5f * c2p;              // pre-halved: r' = 2*relu(u-1)
            g1 = 0.5f * (c1p + c2p);      // factored: B(u) = (u-1)(2g2*u + 2g1)
        }

        u64* dst = g_tab + e * 6;
        dst[0] = dup_bits(a0);
        dst[1] = dup_bits(a1);
        dst[2] = dup_bits(a2);
        dst[3] = dup_bits(g1);
        dst[4] = dup_bits(g2);
        dst[5] = 0ULL;
        return;
    }

    // prologue tables (fp64 once, mirrors reference float64 grid math)
    const double RATIO = 512.0 / 513.0;
    float bb;
    float4* dst;
    if (e < 1728 + 512) {
        int i = e - 1728;
        bb = (float)(((double)i * RATIO / 511.0 - 0.5) * 512.0) * 0.125f + 32.0f;
        dst = &g_pre0[i];
    } else if (e < 1728 + 512 + 1023) {
        int i = e - (1728 + 512);
        bb = (float)(((double)i * RATIO / 1022.0 - 0.5) * 512.0) * 0.125f + 32.0f;
        dst = &g_pre1[i];
    } else {
        return;
    }
    float s0f = fminf(fmaxf(floorf(bb), 0.0f), 63.0f);
    float fb  = bb - s0f;                 // exact
    float d0  = 2.0f * fb - 1.0f;
    int   s3  = (int)s0f * 3;
    *dst = make_float4(0.0f, d0, __int_as_float(s3), 0.0f);
}

__global__ __launch_bounds__(256, 3)
void stripe_poly_kernel(const float* __restrict__ x,
                        float* __restrict__ out)
{
    int pid = blockIdx.x * 256 + threadIdx.x;
    int w = pid >> 9;
    int h = pid & 511;

    // table-driven prologue
    float4 P0 = g_pre0[w];
    float4 P1 = g_pre1[w + h];
    float4 P2 = g_pre1[w - h + 511];

    u64 dd2g[3];
    int idxg[3];
    dd2g[0] = pk(P0.y, P0.y); idxg[0] =        __float_as_int(P0.z);
    dd2g[1] = pk(P1.y, P1.y); idxg[1] = 576  + __float_as_int(P1.z);
    dd2g[2] = pk(P2.y, P2.y); idxg[2] = 1152 + __float_as_int(P2.z);

    const u64 Q2 = pk(0.25f, 0.25f);
    const u64 M1 = pk(-1.0f, -1.0f);
    const u64 ABSM = 0x7fffffff7fffffffULL;

    u64 acc2[4][3];
    #pragma unroll
    for (int p = 0; p < 4; p++)
        #pragma unroll
        for (int o = 0; o < 3; o++)
            acc2[p][o] = 0ULL;

    #pragma unroll
    for (int c = 0; c < 3; c++) {
        float xv[8];
        #pragma unroll
        for (int b = 0; b < 8; b++)
            xv[b] = __ldg(x + (b * 3 + c) * PLANE + pid);
        u64 xv2[4];
        #pragma unroll
        for (int p = 0; p < 4; p++)
            xv2[p] = pk(xv[2 * p], xv[2 * p + 1]);

        #pragma unroll
        for (int g = 0; g < 3; g++) {
            u64 dd2 = dd2g[g];
            const u64* tb = g_tab + (u64)(idxg[g] + c * 192) * 6;

            // u = 0.25x + d0 ; r' = (u-1) + |u-1| = 2*relu(u-1)
            u64 u2[4], r2[4];
            #pragma unroll
            for (int p = 0; p < 4; p++) {
                u2[p] = ffma2(Q2, xv2[p], dd2);
                u64 t = fadd2(u2[p], M1);
                r2[p] = fadd2(t, t & ABSM);
            }

            #pragma unroll
            for (int o = 0; o < 3; o++) {
                const ulonglong2* tp = (const ulonglong2*)(tb + o * 6);
                ulonglong2 v0 = __ldg(tp);       // A0, A1
                ulonglong2 v1 = __ldg(tp + 1);   // A2, G1
                ulonglong2 v2 = __ldg(tp + 2);   // G2, pad
                u64 A0 = v0.x, A1 = v0.y, A2 = v1.x, G1 = v1.y, G2 = v2.x;
                #pragma unroll
                for (int p = 0; p < 4; p++) {
                    u64 hh = ffma2(G2, u2[p], G1);
                    u64 t  = ffma2(A2, u2[p], A1);
                    t      = ffma2(t, u2[p], A0);
                    acc2[p][o] = fadd2(acc2[p][o], t);
                    acc2[p][o] = ffma2(r2[p], hh, acc2[p][o]);
                }
            }
        }
    }

    #pragma unroll
    for (int p = 0; p < 4; p++)
        #pragma unroll
        for (int o = 0; o < 3; o++) {
            float lo, hi;
            upk(acc2[p][o], lo, hi);
            out[((2 * p)     * 3 + o) * PLANE + pid] = lo;
            out[((2 * p + 1) * 3 + o) * PLANE + pid] = hi;
        }
}

extern "C" void kernel_launch(void* const* d_in, const int* in_sizes, int n_in,
                              void* d_out, int out_size)
{
    const float* x  = (const float*)d_in[0];
    const float* Wt = (const float*)d_in[1];
    if (n_in >= 2 && in_sizes[0] == 4644) {
        Wt = (const float*)d_in[0];
        x  = (const float*)d_in[1];
    }
    float* out = (float*)d_out;

    build_kernel<<<13, 256>>>(Wt);     // 1728 table entries + 512 + 1023 prologue
    stripe_poly_kernel<<<(512 * 512) / 256, 256>>>(x, out);
}